// round 14
// baseline (speedup 1.0000x reference)
#include <cuda_runtime.h>

// SmartDerivatives R14: flat multiplicity-1 float4 streaming.
// Multiplicity = lane_stride/load_width; R6/R11/R12 were all 3x (18 L1
// wavefronts per 32 descs). Here lanes load CONTIGUOUS float4s of the raw
// left stream (512B/warp-request, multiplicity 1, no peeling: 29700 floats =
// 7425 float4 exactly, frame base 16B-aligned). float4 f (class = f mod 3)
// carries slots of descs 2*(f/3), 2*(f/3)+1; a shared table gives packed
// (3i | 3j<<16). j-side: per-warp bin RMW (collision-free for rows < 76,
// proven). i-side: warp span <= 23 descs -> uniform-row butterfly reduce /
// two-bucket reduce / lane-serial fallback for the short-row tail.

constexpr int NA    = 100;
constexpr int D     = 4950;
constexpr int E     = D * 6;           // 29700
constexpr int S3    = NA * 3;          // 300
constexpr int WARPS = 10;
constexpr int T     = WARPS * 32;      // 320
constexpr int NF4   = E / 4;           // 7425 float4 per frame
constexpr int ITERS = (NF4 + T - 1) / T;   // 24

__host__ __device__ constexpr int rowbase(int i) { return i * (199 - i) / 2; }

// j-side scatter of one float4 (class-predicated, addresses distinct per lane)
__device__ __forceinline__ void jside(
    bool c0, bool c1, bool c2, unsigned t0, unsigned t1,
    const float4& v, float x0, float x1, float* __restrict__ bw)
{
    if (c0) bw[(t0 >> 16) + 0] += v.w * x0;              // desc0 slot3
    if (c1) {
        const unsigned jb = t0 >> 16;                    // desc0 slots 4,5
        bw[jb + 1] += v.x * x0;
        bw[jb + 2] += v.y * x0;
    }
    if (c2) {
        const unsigned jb = t1 >> 16;                    // desc1 slots 3,4,5
        bw[jb + 0] += v.y * x1;
        bw[jb + 1] += v.z * x1;
        bw[jb + 2] += v.w * x1;
    }
}

__global__ void __launch_bounds__(T, 4)
smart_derivatives_kernel(const float* __restrict__ x,
                         const float* __restrict__ left,
                         float* __restrict__ out) {
    __shared__ unsigned tbl[D];            // 19.8 KB: (3i) | (3j << 16)
    __shared__ float bins[WARPS][S3];      // 12 KB: per-warp accumulators

    const int b    = blockIdx.x;
    const int t    = threadIdx.x;
    const int w    = t >> 5;
    const int lane = t & 31;

    // ---- build desc -> (i,j) table (sqrt estimate + exact integer fixup) ----
    for (int d = t; d < D; d += T) {
        const float s = sqrtf((float)(39601 - 8 * d));
        int i = (int)((199.0f - s) * 0.5f);
        i = i < 0 ? 0 : (i > 98 ? 98 : i);
        while (i > 0 && d < rowbase(i)) --i;
        while (d >= rowbase(i + 1)) ++i;
        const int j = d - rowbase(i) + i + 1;
        tbl[d] = (unsigned)(3 * i) | ((unsigned)(3 * j) << 16);
    }
    for (int k = t; k < WARPS * S3; k += T) (&bins[0][0])[k] = 0.0f;
    __syncthreads();

    const float4* __restrict__ lb4 =
        reinterpret_cast<const float4*>(left + (size_t)b * E);
    const float* __restrict__ xb = x + (size_t)b * D;
    float* __restrict__ bw = bins[w];

    for (int k = 0; k < ITERS; ++k) {
        const int  f     = k * T + t;
        const bool valid = (f < NF4);
        if (!__any_sync(0xffffffffu, valid)) break;

        const int fc  = valid ? f : NF4 - 1;      // clamp (contributions zeroed)
        const int q   = fc / 3;
        const int cls = fc - 3 * q;
        const int d0  = 2 * q, d1 = d0 + 1;

        const float4   v  = __ldcs(lb4 + fc);     // multiplicity-1 stream
        const float    x0 = __ldg(xb + d0);
        const float    x1 = __ldg(xb + d1);
        const unsigned t0 = tbl[d0];
        const unsigned t1 = tbl[d1];

        const bool c0 = valid && (cls == 0);
        const bool c1 = valid && (cls == 1);
        const bool c2 = valid && (cls == 2);

        // i-side contribution of this float4 (single i per lane)
        float a0 = 0.f, a1 = 0.f, a2 = 0.f;
        if (c0) { a0 = v.x * x0; a1 = v.y * x0; a2 = v.z * x0; }  // desc0 slots 0..2
        if (c1) { a0 = v.z * x1; a1 = v.w * x1; }                 // desc1 slots 0,1
        if (c2) { a2 = v.x * x1; }                                // desc1 slot 2
        int ibin = c0 ? (int)(t0 & 0xFFFFu) : (int)(t1 & 0xFFFFu);
        if (!valid) ibin = 1 << 20;                               // force serial path

        const int iF = __shfl_sync(0xffffffffu, ibin, 0);
        const int iL = __shfl_sync(0xffffffffu, ibin, 31);

        if (iF == iL) {
            // whole warp in one row: butterfly reduce, one lane commits
            jside(c0, c1, c2, t0, t1, v, x0, x1, bw);
            #pragma unroll
            for (int o = 16; o; o >>= 1) {
                a0 += __shfl_xor_sync(0xffffffffu, a0, o);
                a1 += __shfl_xor_sync(0xffffffffu, a1, o);
                a2 += __shfl_xor_sync(0xffffffffu, a2, o);
            }
            if (lane == 0) {
                bw[iF + 0] += a0; bw[iF + 1] += a1; bw[iF + 2] += a2;
            }
        } else if (iL == iF + 3 && iF < 225) {
            // exactly two rows, both long enough that j's stay distinct
            jside(c0, c1, c2, t0, t1, v, x0, x1, bw);
            const bool toB = (ibin != iF);
            float b0 = toB ? a0 : 0.f; a0 = toB ? 0.f : a0;
            float b1 = toB ? a1 : 0.f; a1 = toB ? 0.f : a1;
            float b2 = toB ? a2 : 0.f; a2 = toB ? 0.f : a2;
            #pragma unroll
            for (int o = 16; o; o >>= 1) {
                a0 += __shfl_xor_sync(0xffffffffu, a0, o);
                a1 += __shfl_xor_sync(0xffffffffu, a1, o);
                a2 += __shfl_xor_sync(0xffffffffu, a2, o);
                b0 += __shfl_xor_sync(0xffffffffu, b0, o);
                b1 += __shfl_xor_sync(0xffffffffu, b1, o);
                b2 += __shfl_xor_sync(0xffffffffu, b2, o);
            }
            if (lane == 0) {
                bw[iF + 0] += a0; bw[iF + 1] += a1; bw[iF + 2] += a2;
                bw[iF + 3] += b0; bw[iF + 4] += b1; bw[iF + 5] += b2;
            }
        } else {
            // short-row tail / partial warp: lane-serialized commit
            for (int l = 0; l < 32; ++l) {
                if (lane == l && valid) {
                    bw[ibin + 0] += a0; bw[ibin + 1] += a1; bw[ibin + 2] += a2;
                    jside(c0, c1, c2, t0, t1, v, x0, x1, bw);
                }
                __syncwarp();
            }
        }
    }
    __syncthreads();

    // combine: out(a,d) = (sum over warps of bins)^2, coalesced store
    if (t < S3) {
        float s = 0.0f;
        #pragma unroll
        for (int ww = 0; ww < WARPS; ++ww) s += bins[ww][t];
        out[(size_t)b * S3 + t] = s * s;
    }
}

extern "C" void kernel_launch(void* const* d_in, const int* in_sizes, int n_in,
                              void* d_out, int out_size) {
    const float* x    = (const float*)d_in[0];   // [BATCH, D] fp32
    const float* left = (const float*)d_in[1];   // [BATCH*E] fp32
    (void)in_sizes; (void)n_in; (void)out_size;

    float* out = (float*)d_out;                  // [BATCH, 300] fp32
    smart_derivatives_kernel<<<1024, T>>>(x, left, out);
}

// round 15
// speedup vs baseline: 2.0829x; 2.0829x over previous
#include <cuda_runtime.h>

// SmartDerivatives R15 = R11 (champion, 39.0us) locked at the modeled floor.
// Port-crossing model (validated on R6/R9/R11/R12/R14): per 32 descs the SM's
// 128B L1/shared port must move >= 768B of left (6 crossings minimum; R11's
// stride-24B LDG.64 delivery = 18, and any smem bounce = 6+6+6 = 18 too),
// + 6 RMW + 1 x  => ~25 crossings * 1412 warp-iters/SM * ~2cyc ~= 39us.
// Tweaks vs R11: longer row of each mirrored pair issues first (pipeline
// fill), explicit occupancy floor in launch_bounds. Structure unchanged:
// 320 thr, direct LDG (__ldcs streaming on left), i-side register accum +
// shfl reduce, j-side warp-private bins (stride-3 RMW, conflict-free).

constexpr int NA    = 100;
constexpr int D     = 4950;          // triu descriptors
constexpr int E     = D * 6;
constexpr int S3    = NA * 3;        // 300 outputs / frame
constexpr int WARPS = 10;
constexpr int T     = WARPS * 32;    // 320 threads

__device__ __forceinline__ void process_row(
    int i, int lane,
    const float* __restrict__ lb, const float* __restrict__ xb,
    float* __restrict__ ca, float* __restrict__ rowout)
{
    const int base = (i * (2 * NA - i - 1)) >> 1;  // row start desc
    const int len  = NA - 1 - i;                   // descs in row

    float r0 = 0.0f, r1 = 0.0f, r2 = 0.0f;

    #pragma unroll 4
    for (int m = lane; m < len; m += 32) {
        const int desc = base + m;
        const float2* lp = reinterpret_cast<const float2*>(lb + desc * 6);
        const float2 l01 = __ldcs(lp);         // streaming: read-once data
        const float2 l23 = __ldcs(lp + 1);
        const float2 l45 = __ldcs(lp + 2);
        const float  xv  = __ldg(xb + desc);   // cached: reused across rows

        // atom-i side (slots 0..2)
        r0 = fmaf(l01.x, xv, r0);
        r1 = fmaf(l01.y, xv, r1);
        r2 = fmaf(l23.x, xv, r2);

        // atom-j side (slots 3..5): j unique per lane -> conflict-free RMW
        float* cj = ca + (i + 1 + m) * 3;
        cj[0] += l23.y * xv;
        cj[1] += l45.x * xv;
        cj[2] += l45.y * xv;
    }

    #pragma unroll
    for (int off = 16; off; off >>= 1) {
        r0 += __shfl_down_sync(0xffffffffu, r0, off);
        r1 += __shfl_down_sync(0xffffffffu, r1, off);
        r2 += __shfl_down_sync(0xffffffffu, r2, off);
    }
    if (lane == 0) {
        rowout[i * 3 + 0] = r0;
        rowout[i * 3 + 1] = r1;
        rowout[i * 3 + 2] = r2;
    }
}

__global__ void __launch_bounds__(T, 6)
smart_derivatives_kernel(const float* __restrict__ x,
                         const float* __restrict__ left,
                         float* __restrict__ out) {
    __shared__ float colacc[WARPS][S3];  // 12 KB: per-warp j-side bins
    __shared__ float rowout[S3];         // 1.2 KB: i-side row sums

    const int b    = blockIdx.x;
    const int t    = threadIdx.x;
    const int w    = t >> 5;
    const int lane = t & 31;

    // zero accumulators
    for (int i = t; i < WARPS * S3; i += T) (&colacc[0][0])[i] = 0.0f;
    if (t < S3) rowout[t] = 0.0f;
    __syncthreads();

    const float* __restrict__ lb = left + (size_t)b * E;
    const float* __restrict__ xb = x + (size_t)b * D;
    float* __restrict__ ca = colacc[w];

    // Mirrored pairing per 20-row band: rows (base+w) and (base+19-w);
    // pair lengths sum to a constant -> perfect warp balance.
    // Longer (lower-index) row first: its load stream fills the pipeline.
    for (int base = 0; base < NA - 1; base += 2 * WARPS) {
        const int i1 = base + w;                     // longer row
        const int i2 = base + (2 * WARPS - 1) - w;   // shorter row
        if (i1 < NA - 1) process_row(i1, lane, lb, xb, ca, rowout);
        if (i2 < NA - 1) process_row(i2, lane, lb, xb, ca, rowout);
    }
    __syncthreads();

    // combine: out(a,d) = (rowout + sum_w colacc[w])^2, coalesced store
    if (t < S3) {
        float s = rowout[t];
        #pragma unroll
        for (int ww = 0; ww < WARPS; ++ww) s += colacc[ww][t];
        out[(size_t)b * S3 + t] = s * s;
    }
}

extern "C" void kernel_launch(void* const* d_in, const int* in_sizes, int n_in,
                              void* d_out, int out_size) {
    const float* x    = (const float*)d_in[0];   // [BATCH, D] fp32
    const float* left = (const float*)d_in[1];   // [BATCH*E] fp32
    (void)in_sizes; (void)n_in; (void)out_size;

    float* out = (float*)d_out;                  // [BATCH, 300] fp32
    smart_derivatives_kernel<<<1024, T>>>(x, left, out);
}

// round 16
// speedup vs baseline: 2.3225x; 1.1150x over previous
#include <cuda_runtime.h>

// SmartDerivatives R16 = R11/R15 structure + explicit load front-batching.
// R15 evidence: regs=32 with "unroll 4" means ptxas interleaved load->FMA,
// leaving only ~4-7 outstanding LDGs/warp -> MLP-starved latency bind (no
// pipe >51%). A triu row has at most 3 full-warp iterations (len>>5 <= 3),
// so batches are straight-line: issue ALL of a row's full-iteration loads
// (9 float2 + 3 x = up to 21) before any math, then the math, then a masked
// tail. launch_bounds(320,5) caps regs at 40 (5 CTAs/SM, 50 warps).
// Consumer math unchanged: i-side register accum + shfl reduce; j-side
// warp-private bins, stride-3 RMW (conflict-free); mirrored row pairs.

constexpr int NA    = 100;
constexpr int D     = 4950;
constexpr int E     = D * 6;
constexpr int S3    = NA * 3;        // 300
constexpr int WARPS = 10;
constexpr int T     = WARPS * 32;    // 320

__device__ __forceinline__ void desc_math(
    float2 l01, float2 l23, float2 l45, float xv, int j,
    float& r0, float& r1, float& r2, float* __restrict__ ca)
{
    r0 = fmaf(l01.x, xv, r0);
    r1 = fmaf(l01.y, xv, r1);
    r2 = fmaf(l23.x, xv, r2);
    float* cj = ca + j * 3;
    cj[0] += l23.y * xv;
    cj[1] += l45.x * xv;
    cj[2] += l45.y * xv;
}

__device__ __forceinline__ void process_row(
    int i, int lane,
    const float* __restrict__ lb, const float* __restrict__ xb,
    float* __restrict__ ca, float* __restrict__ rowout)
{
    const int base = (i * (2 * NA - i - 1)) >> 1;
    const int len  = NA - 1 - i;

    const float2* __restrict__ lp =
        reinterpret_cast<const float2*>(lb + (size_t)base * 6);  // idx 3*m
    const float* __restrict__ xr = xb + base;

    float r0 = 0.0f, r1 = 0.0f, r2 = 0.0f;
    int m = lane;
    const int kf = len >> 5;          // full-warp iterations: 0..3 (warp-uniform)

    if (kf >= 3) {
        // ---- all loads first (21 outstanding) ----
        const float2 A0 = __ldcs(lp + 3 * m),        A1 = __ldcs(lp + 3 * m + 1),        A2 = __ldcs(lp + 3 * m + 2);
        const float2 B0 = __ldcs(lp + 3 * (m + 32)), B1 = __ldcs(lp + 3 * (m + 32) + 1), B2 = __ldcs(lp + 3 * (m + 32) + 2);
        const float2 C0 = __ldcs(lp + 3 * (m + 64)), C1 = __ldcs(lp + 3 * (m + 64) + 1), C2 = __ldcs(lp + 3 * (m + 64) + 2);
        const float  xa = __ldg(xr + m), xb2 = __ldg(xr + m + 32), xc = __ldg(xr + m + 64);
        // ---- then math ----
        desc_math(A0, A1, A2, xa,  i + 1 + m,      r0, r1, r2, ca);
        desc_math(B0, B1, B2, xb2, i + 1 + m + 32, r0, r1, r2, ca);
        desc_math(C0, C1, C2, xc,  i + 1 + m + 64, r0, r1, r2, ca);
        m += 96;
    } else if (kf == 2) {
        const float2 A0 = __ldcs(lp + 3 * m),        A1 = __ldcs(lp + 3 * m + 1),        A2 = __ldcs(lp + 3 * m + 2);
        const float2 B0 = __ldcs(lp + 3 * (m + 32)), B1 = __ldcs(lp + 3 * (m + 32) + 1), B2 = __ldcs(lp + 3 * (m + 32) + 2);
        const float  xa = __ldg(xr + m), xb2 = __ldg(xr + m + 32);
        desc_math(A0, A1, A2, xa,  i + 1 + m,      r0, r1, r2, ca);
        desc_math(B0, B1, B2, xb2, i + 1 + m + 32, r0, r1, r2, ca);
        m += 64;
    } else if (kf == 1) {
        const float2 A0 = __ldcs(lp + 3 * m), A1 = __ldcs(lp + 3 * m + 1), A2 = __ldcs(lp + 3 * m + 2);
        const float  xa = __ldg(xr + m);
        desc_math(A0, A1, A2, xa, i + 1 + m, r0, r1, r2, ca);
        m += 32;
    }

    if (m < len) {                    // masked tail iteration
        const float2 A0 = __ldcs(lp + 3 * m), A1 = __ldcs(lp + 3 * m + 1), A2 = __ldcs(lp + 3 * m + 2);
        const float  xa = __ldg(xr + m);
        desc_math(A0, A1, A2, xa, i + 1 + m, r0, r1, r2, ca);
    }

    #pragma unroll
    for (int off = 16; off; off >>= 1) {
        r0 += __shfl_down_sync(0xffffffffu, r0, off);
        r1 += __shfl_down_sync(0xffffffffu, r1, off);
        r2 += __shfl_down_sync(0xffffffffu, r2, off);
    }
    if (lane == 0) {
        rowout[i * 3 + 0] = r0;
        rowout[i * 3 + 1] = r1;
        rowout[i * 3 + 2] = r2;
    }
}

__global__ void __launch_bounds__(T, 5)
smart_derivatives_kernel(const float* __restrict__ x,
                         const float* __restrict__ left,
                         float* __restrict__ out) {
    __shared__ float colacc[WARPS][S3];  // 12 KB: per-warp j-side bins
    __shared__ float rowout[S3];         // 1.2 KB

    const int b    = blockIdx.x;
    const int t    = threadIdx.x;
    const int w    = t >> 5;
    const int lane = t & 31;

    for (int i = t; i < WARPS * S3; i += T) (&colacc[0][0])[i] = 0.0f;
    if (t < S3) rowout[t] = 0.0f;
    __syncthreads();

    const float* __restrict__ lb = left + (size_t)b * E;
    const float* __restrict__ xb = x + (size_t)b * D;
    float* __restrict__ ca = colacc[w];

    // Mirrored pairing per 20-row band: rows (base+w) and (base+19-w);
    // longer row first (its loads fill the pipeline).
    for (int base = 0; base < NA - 1; base += 2 * WARPS) {
        const int i1 = base + w;
        const int i2 = base + (2 * WARPS - 1) - w;
        if (i1 < NA - 1) process_row(i1, lane, lb, xb, ca, rowout);
        if (i2 < NA - 1) process_row(i2, lane, lb, xb, ca, rowout);
    }
    __syncthreads();

    if (t < S3) {
        float s = rowout[t];
        #pragma unroll
        for (int ww = 0; ww < WARPS; ++ww) s += colacc[ww][t];
        out[(size_t)b * S3 + t] = s * s;
    }
}

extern "C" void kernel_launch(void* const* d_in, const int* in_sizes, int n_in,
                              void* d_out, int out_size) {
    const float* x    = (const float*)d_in[0];   // [BATCH, D] fp32
    const float* left = (const float*)d_in[1];   // [BATCH*E] fp32
    (void)in_sizes; (void)n_in; (void)out_size;

    float* out = (float*)d_out;                  // [BATCH, 300] fp32
    smart_derivatives_kernel<<<1024, T>>>(x, left, out);
}

// round 17
// speedup vs baseline: 2.5015x; 1.0771x over previous
#include <cuda_runtime.h>

// SmartDerivatives R17 = R16 + merged-pair front-batching (deeper MLP).
// R16 confirmed the MLP model (35.3us, no pipe >51% -> latency-bound).
// Each warp's mirrored row pair (i1=base+w, i2=base+19-w) has
// kf1+kf2 <= 5 full warp-iterations total (len1+len2 = 179-2*base).
// All slots' loads (up to 5*(3 LDG.64 + 1 LDG.32) = 35 values) issue in one
// straight-line block with warp-uniform guards, then all math, then 2 masked
// tails. launch_bounds(320,4) = 51-reg cap, 40 warps/SM.
// Math unchanged: i-side register accum + shfl reduce (per row); j-side
// warp-private bins, stride-3 RMW (conflict-free); __ldcs left stream.

constexpr int NA    = 100;
constexpr int D     = 4950;
constexpr int E     = D * 6;
constexpr int S3    = NA * 3;        // 300
constexpr int WARPS = 10;
constexpr int T     = WARPS * 32;    // 320

__device__ __forceinline__ int rowbase(int i) { return (i * (199 - i)) >> 1; }

__device__ __forceinline__ void desc_math(
    float2 l01, float2 l23, float2 l45, float xv, int j,
    float& r0, float& r1, float& r2, float* __restrict__ ca)
{
    r0 = fmaf(l01.x, xv, r0);
    r1 = fmaf(l01.y, xv, r1);
    r2 = fmaf(l23.x, xv, r2);
    float* cj = ca + j * 3;
    cj[0] += l23.y * xv;
    cj[1] += l45.x * xv;
    cj[2] += l45.y * xv;
}

__global__ void __launch_bounds__(T, 4)
smart_derivatives_kernel(const float* __restrict__ x,
                         const float* __restrict__ left,
                         float* __restrict__ out) {
    __shared__ float colacc[WARPS][S3];  // 12 KB: per-warp j-side bins
    __shared__ float rowout[S3];         // 1.2 KB

    const int b    = blockIdx.x;
    const int t    = threadIdx.x;
    const int w    = t >> 5;
    const int lane = t & 31;

    for (int i = t; i < WARPS * S3; i += T) (&colacc[0][0])[i] = 0.0f;
    if (t < S3) rowout[t] = 0.0f;
    __syncthreads();

    const float2* __restrict__ lb2 =
        reinterpret_cast<const float2*>(left + (size_t)b * E);
    const float* __restrict__ xb = x + (size_t)b * D;
    float* __restrict__ ca = colacc[w];

    #pragma unroll
    for (int base = 0; base < NA - 1; base += 2 * WARPS) {
        const int i1   = base + w;                   // long row (always valid)
        const int i2   = base + (2 * WARPS - 1) - w; // short row (len may be 0)
        const int len1 = NA - 1 - i1;
        const int len2 = (i2 < NA - 1) ? (NA - 1 - i2) : 0;
        const int b1   = rowbase(i1);                // desc base row1
        const int b2   = (len2 > 0) ? rowbase(i2) : b1;
        const int kf1  = len1 >> 5;                  // full iters row1 (0..3)
        const int kf2  = len2 >> 5;                  // full iters row2 (0..3)
        const int K    = kf1 + kf2;                  // <= 5, warp-uniform

        // slot s -> (row, m): s<kf1 -> row1, m = lane+32s
        //                     else  -> row2, m = lane+32(s-kf1)
        float2 A[5], B[5], C[5];
        float  X[5];

        // ---- load phase: all slots' loads issued back-to-back ----
        #pragma unroll
        for (int s = 0; s < 5; ++s) {
            if (s < K) {
                const bool f = (s < kf1);
                const int  m = lane + ((f ? s : s - kf1) << 5);
                const int  o = (f ? b1 : b2) + m;    // desc index
                A[s] = __ldcs(lb2 + 3 * o);
                B[s] = __ldcs(lb2 + 3 * o + 1);
                C[s] = __ldcs(lb2 + 3 * o + 2);
                X[s] = __ldg(xb + o);
            }
        }

        // ---- math phase ----
        float r0 = 0.f, r1 = 0.f, r2 = 0.f;   // row1 accumulators
        float s0 = 0.f, s1 = 0.f, s2 = 0.f;   // row2 accumulators
        #pragma unroll
        for (int s = 0; s < 5; ++s) {
            if (s < K) {
                const bool f = (s < kf1);
                const int  m = lane + ((f ? s : s - kf1) << 5);
                const int  j = (f ? i1 : i2) + 1 + m;
                if (f) desc_math(A[s], B[s], C[s], X[s], j, r0, r1, r2, ca);
                else   desc_math(A[s], B[s], C[s], X[s], j, s0, s1, s2, ca);
            }
        }

        // ---- masked tails (one per row) ----
        {
            const int m = (kf1 << 5) + lane;
            if (m < len1) {
                const int o = b1 + m;
                const float2 a = __ldcs(lb2 + 3 * o), bb = __ldcs(lb2 + 3 * o + 1),
                             cc = __ldcs(lb2 + 3 * o + 2);
                desc_math(a, bb, cc, __ldg(xb + o), i1 + 1 + m, r0, r1, r2, ca);
            }
        }
        {
            const int m = (kf2 << 5) + lane;
            if (m < len2) {
                const int o = b2 + m;
                const float2 a = __ldcs(lb2 + 3 * o), bb = __ldcs(lb2 + 3 * o + 1),
                             cc = __ldcs(lb2 + 3 * o + 2);
                desc_math(a, bb, cc, __ldg(xb + o), i2 + 1 + m, s0, s1, s2, ca);
            }
        }

        // ---- per-row reductions ----
        #pragma unroll
        for (int off = 16; off; off >>= 1) {
            r0 += __shfl_down_sync(0xffffffffu, r0, off);
            r1 += __shfl_down_sync(0xffffffffu, r1, off);
            r2 += __shfl_down_sync(0xffffffffu, r2, off);
            s0 += __shfl_down_sync(0xffffffffu, s0, off);
            s1 += __shfl_down_sync(0xffffffffu, s1, off);
            s2 += __shfl_down_sync(0xffffffffu, s2, off);
        }
        if (lane == 0) {
            rowout[i1 * 3 + 0] = r0;
            rowout[i1 * 3 + 1] = r1;
            rowout[i1 * 3 + 2] = r2;
            if (len2 > 0) {
                rowout[i2 * 3 + 0] = s0;
                rowout[i2 * 3 + 1] = s1;
                rowout[i2 * 3 + 2] = s2;
            }
        }
    }
    __syncthreads();

    // combine: out(a,d) = (rowout + sum_w colacc[w])^2, coalesced store
    if (t < S3) {
        float s = rowout[t];
        #pragma unroll
        for (int ww = 0; ww < WARPS; ++ww) s += colacc[ww][t];
        out[(size_t)b * S3 + t] = s * s;
    }
}

extern "C" void kernel_launch(void* const* d_in, const int* in_sizes, int n_in,
                              void* d_out, int out_size) {
    const float* x    = (const float*)d_in[0];   // [BATCH, D] fp32
    const float* left = (const float*)d_in[1];   // [BATCH*E] fp32
    (void)in_sizes; (void)n_in; (void)out_size;

    float* out = (float*)d_out;                  // [BATCH, 300] fp32
    smart_derivatives_kernel<<<1024, T>>>(x, left, out);
}